// round 15
// baseline (speedup 1.0000x reference)
#include <cuda_runtime.h>
#include <cuda_fp16.h>
#include <math.h>
#include <stdint.h>

// Problem constants
#define BB   2
#define SS   2048
#define HID  2048
#define NH   16
#define NKV  4
#define HD   128
#define MTOK (BB*SS)          // 4096
#define QDIM (NH*HD)          // 2048
#define KVDIM (NKV*HD)        // 512
#define QKVD (QDIM + 2*KVDIM) // 3072
#define NQ   (SS/128)         // 16 q-tiles per (b)

#define WSCALE    64.0f
#define INV_WSCALE 0.015625f

// ---------------------------------------------------------------------------
// Scratch (device globals; no allocation allowed)
// ---------------------------------------------------------------------------
__device__ __half g_C16[(size_t)MTOK * QKVD];              // fused QKV fp16 (roped at store)
__device__ __half g_H16[(size_t)MTOK * HID];               // hidden fp16
__device__ __half g_W16[(size_t)QKVD * HID];               // packed QKV weights x64
__device__ __half g_Wo16[(size_t)HID * QDIM];              // Wo x64
__device__ __half g_O16[(size_t)MTOK * QDIM];              // combined attn out fp16
__device__ __half g_Op[2 * (size_t)MTOK * QDIM];           // split-KV partial O (normalized)
__device__ float2 g_ml[2 * (size_t)MTOK * NH];             // split-KV partial (m, l)
__device__ float2 g_cs[(size_t)SS * 64];                   // rope (cos,sin) table [pos][i]

// ---------------------------------------------------------------------------
// helpers
// ---------------------------------------------------------------------------
__device__ __forceinline__ uint32_t smem_to_u32(const void* p) {
    uint32_t a;
    asm("{ .reg .u64 t; cvta.to.shared.u64 t, %1; cvt.u32.u64 %0, t; }"
        : "=r"(a) : "l"(p));
    return a;
}
__device__ __forceinline__ uint32_t pack_h2(__half a, __half b) {
    return (uint32_t)__half_as_ushort(a) | ((uint32_t)__half_as_ushort(b) << 16);
}

#define LDMX4(r, addr) \
    asm volatile("ldmatrix.sync.aligned.m8n8.x4.shared.b16 {%0,%1,%2,%3}, [%4];" \
        : "=r"((r)[0]), "=r"((r)[1]), "=r"((r)[2]), "=r"((r)[3]) : "r"(addr))
#define LDMX4T(r, addr) \
    asm volatile("ldmatrix.sync.aligned.m8n8.x4.trans.shared.b16 {%0,%1,%2,%3}, [%4];" \
        : "=r"((r)[0]), "=r"((r)[1]), "=r"((r)[2]), "=r"((r)[3]) : "r"(addr))
#define MMA_F16(c, a, b0, b1) \
    asm volatile("mma.sync.aligned.m16n8k16.row.col.f32.f16.f16.f32 " \
        "{%0,%1,%2,%3},{%4,%5,%6,%7},{%8,%9},{%0,%1,%2,%3};" \
        : "+f"((c)[0]), "+f"((c)[1]), "+f"((c)[2]), "+f"((c)[3]) \
        : "r"((a)[0]), "r"((a)[1]), "r"((a)[2]), "r"((a)[3]), "r"(b0), "r"(b1))

__device__ __forceinline__ void cp16(uint32_t dst, const void* src) {
    asm volatile("cp.async.cg.shared.global [%0], [%1], 16;" :: "r"(dst), "l"(src));
}
#define CP_COMMIT() asm volatile("cp.async.commit_group;" ::: "memory")
#define CP_WAIT(n)  asm volatile("cp.async.wait_group %0;" :: "n"(n) : "memory")

// ---------------------------------------------------------------------------
// conversion kernel: all fp32 -> fp16 inputs + rope (cos,sin) table build
// regions: hidden(x1) | Wq(x64) | Wk(x64) | Wv(x64) | Wo(x64) | rope table
// ---------------------------------------------------------------------------
#define CN0 (MTOK * HID / 4)     // hidden
#define CN1 (QDIM * HID / 4)     // Wq
#define CN2 (KVDIM * HID / 4)    // Wk
#define CN3 (KVDIM * HID / 4)    // Wv
#define CN4 (HID * QDIM / 4)     // Wo
#define CNT (CN0 + CN1 + CN2 + CN3 + CN4)
#define CTBL (SS * 64)           // rope table entries
#define CALL (CNT + CTBL)

__global__ void conv_all(const float* __restrict__ hid, const float* __restrict__ wq,
                         const float* __restrict__ wk, const float* __restrict__ wv,
                         const float* __restrict__ wo,
                         __half* __restrict__ H16, __half* __restrict__ W16,
                         __half* __restrict__ Wo16, float2* __restrict__ cs)
{
    int i = blockIdx.x * blockDim.x + threadIdx.x;
    if (i >= CALL) return;
    if (i >= CNT) {
        // rope table: entry (pos, ii)
        int idx = i - CNT;
        int pos = idx >> 6;
        int ii  = idx & 63;
        double invf = exp(-(double)ii * 0.14391156831212787);  // ln(10000)/64
        double ang = (double)pos * invf;
        double k = rint(ang * 0.15915494309189535);
        float r = (float)(ang - k * 6.283185307179586477);
        float sv, cv;
        sincosf(r, &sv, &cv);
        cs[idx] = make_float2(cv, sv);
        return;
    }
    const float* src;
    __half* dst;
    int j;
    float sc;
    if (i < CN0)                 { src = hid; dst = H16; j = i; sc = 1.f; }
    else if (i < CN0 + CN1)      { src = wq;  dst = W16; j = i - CN0; sc = WSCALE; }
    else if (i < CN0 + CN1 + CN2){ src = wk;  dst = W16 + (size_t)QDIM * HID;
                                   j = i - CN0 - CN1; sc = WSCALE; }
    else if (i < CN0 + CN1 + CN2 + CN3)
                                 { src = wv;  dst = W16 + (size_t)(QDIM + KVDIM) * HID;
                                   j = i - CN0 - CN1 - CN2; sc = WSCALE; }
    else                         { src = wo;  dst = Wo16;
                                   j = i - CN0 - CN1 - CN2 - CN3; sc = WSCALE; }
    float4 v = ((const float4*)src)[j];
    ((uint2*)dst)[j] = make_uint2(
        pack_h2(__float2half_rn(v.x * sc), __float2half_rn(v.y * sc)),
        pack_h2(__float2half_rn(v.z * sc), __float2half_rn(v.w * sc)));
}

// ---------------------------------------------------------------------------
// GEMM core: CTA 128x128, BK=32, 256 thr, 8 warps (warp 64x32).
// 4-stage cp.async pipeline, one __syncthreads per K-iteration.
// ---------------------------------------------------------------------------
#define SROW   40
#define TPART  (128 * SROW * 2)        // 10240 B
#define TSTAGE (2 * TPART)             // 20480 B
#define GEMM_SMEM (4 * TSTAGE)         // 81920 B
#define EROWF  133                     // fp32 epilogue smem row stride (pad)

#define GEMM_COMPUTE(kt) do { \
    const uint32_t base_ = sbase + (uint32_t)((kt) & 3) * TSTAGE; \
    _Pragma("unroll") \
    for (int ks = 0; ks < 2; ks++) { \
        const uint32_t kb = ks * 32; \
        uint32_t ah[4][4], bh2[2][4]; \
        _Pragma("unroll") \
        for (int mf = 0; mf < 4; mf++) \
            LDMX4(ah[mf], base_ + a_lane + mf * 16 * (SROW * 2) + kb); \
        _Pragma("unroll") \
        for (int nf2 = 0; nf2 < 2; nf2++) \
            LDMX4(bh2[nf2], base_ + TPART + b_lane + nf2 * 16 * (SROW * 2) + kb); \
        _Pragma("unroll") \
        for (int mf = 0; mf < 4; mf++) \
            _Pragma("unroll") \
            for (int nf = 0; nf < 4; nf++) \
                MMA_F16(acc[mf][nf], ah[mf], \
                        bh2[nf >> 1][nf & 1], bh2[nf >> 1][(nf & 1) + 2]); \
    } \
} while (0)

#define GEMM_MAIN() \
    float acc[4][4][4]; \
    _Pragma("unroll") \
    for (int mf = 0; mf < 4; mf++) \
        _Pragma("unroll") \
        for (int nf = 0; nf < 4; nf++) \
            _Pragma("unroll") \
            for (int r = 0; r < 4; r++) acc[mf][nf][r] = 0.f; \
    G_ISSUE(0, 0); CP_COMMIT(); \
    G_ISSUE(1, 1); CP_COMMIT(); \
    G_ISSUE(2, 2); CP_COMMIT(); \
    const int lr16 = lane & 15; \
    const int lh   = lane >> 4; \
    const uint32_t a_lane = (uint32_t)((wm * 64 + lr16) * (SROW * 2) + lh * 16); \
    const uint32_t b_lane = (uint32_t)((wn * 32 + lr16) * (SROW * 2) + lh * 16); \
    for (int kt = 0; kt < NKT; kt++) { \
        if (kt + 3 <= NKT)       CP_WAIT(2); \
        else if (kt + 2 == NKT)  CP_WAIT(1); \
        else                     CP_WAIT(0); \
        __syncthreads(); \
        if (kt + 3 < NKT) { G_ISSUE(kt + 3, (kt + 3) & 3); CP_COMMIT(); } \
        GEMM_COMPUTE(kt); \
    }

#define G_ISSUE(kt, buf) do { \
    uint32_t db = sbase + (uint32_t)(buf) * TSTAGE; \
    cp16(db + cr0 * 80 + cc0, \
         A + (size_t)(bm + cr0) * K + (kt) * 32 + (cc0 >> 1)); \
    cp16(db + cr1 * 80 + cc0, \
         A + (size_t)(bm + cr1) * K + (kt) * 32 + (cc0 >> 1)); \
    cp16(db + TPART + cr0 * 80 + cc0, \
         B + (size_t)(bn + cr0) * K + (kt) * 32 + (cc0 >> 1)); \
    cp16(db + TPART + cr1 * 80 + cc0, \
         B + (size_t)(bn + cr1) * K + (kt) * 32 + (cc0 >> 1)); \
} while (0)

// ---------------------------------------------------------------------------
// QKV projection GEMM with FUSED RoPE epilogue.
// Every 128-col block is one head (Q or K) or a V block. fp32 accumulators
// go through smem; rope rotation uses the precomputed (cos,sin) table; fp16
// is rounded ONCE at the end (more accurate than the old rope-after-round).
// ---------------------------------------------------------------------------
__global__ __launch_bounds__(256, 2) void gemm_qkv(
    const __half* __restrict__ A, const __half* __restrict__ B,
    __half* __restrict__ C, int M, int N, int K, float outscale,
    const int* __restrict__ pos_ids, const float2* __restrict__ cs)
{
    extern __shared__ char smem[];
    const uint32_t sbase = smem_to_u32(smem);
    const int tid  = threadIdx.x;
    const int wid  = tid >> 5;
    const int lane = tid & 31;
    const int wm   = wid >> 2;
    const int wn   = wid & 3;
    const int bm   = blockIdx.y * 128;
    const int bn   = blockIdx.x * 128;
    const int NKT  = K / 32;
    const int cr0 = tid >> 2, cc0 = (tid & 3) * 16;
    const int cr1 = (tid + 256) >> 2;

    GEMM_MAIN();

    // ---- epilogue: accum -> smem (fp32) -> rope -> fp16 store
    __syncthreads();          // all warps done reading pipeline stages
    float* sm32 = (float*)smem;
    {
        const int rl = wm * 64 + (lane >> 2);
        const int cl = wn * 32 + (lane & 3) * 2;
#pragma unroll
        for (int mf = 0; mf < 4; mf++)
#pragma unroll
            for (int nf = 0; nf < 4; nf++) {
                float* c = acc[mf][nf];
                int r0 = rl + mf * 16;
                int cc = cl + nf * 8;
                sm32[r0 * EROWF + cc]           = c[0] * outscale;
                sm32[r0 * EROWF + cc + 1]       = c[1] * outscale;
                sm32[(r0 + 8) * EROWF + cc]     = c[2] * outscale;
                sm32[(r0 + 8) * EROWF + cc + 1] = c[3] * outscale;
            }
    }
    __syncthreads();

    const int r  = tid >> 1;             // local row 0..127
    const int g  = (tid & 1) * 32;       // col group 0 or 32
    const int token = bm + r;
    __half* dst = C + (size_t)token * N + bn;

    if (bn < QDIM + KVDIM) {
        // Q or K head block: apply rope to pairs (i, i+64)
        const float2* csr = cs + (size_t)pos_ids[token] * 64;
        uint32_t o1[16], o2[16];
#pragma unroll
        for (int j = 0; j < 32; j += 2) {
            int i0 = g + j, i1 = i0 + 1;
            float x1a = sm32[r * EROWF + i0];
            float x2a = sm32[r * EROWF + i0 + 64];
            float x1b = sm32[r * EROWF + i1];
            float x2b = sm32[r * EROWF + i1 + 64];
            float2 ca = csr[i0];
            float2 cb = csr[i1];
            float y1a = x1a * ca.x - x2a * ca.y;
            float y2a = x2a * ca.x + x1a * ca.y;
            float y1b = x1b * cb.x - x2b * cb.y;
            float y2b = x2b * cb.x + x1b * cb.y;
            o1[j >> 1] = pack_h2(__float2half_rn(y1a), __float2half_rn(y1b));
            o2[j >> 1] = pack_h2(__float2half_rn(y2a), __float2half_rn(y2b));
        }
#pragma unroll
        for (int j = 0; j < 16; j++) {
            ((uint32_t*)(dst + g))[j]      = o1[j];
            ((uint32_t*)(dst + g + 64))[j] = o2[j];
        }
    } else {
        // V block: straight fp16 convert (both col groups g and g+64)
        uint32_t o1[16], o2[16];
#pragma unroll
        for (int j = 0; j < 32; j += 2) {
            int i0 = g + j, i1 = i0 + 1;
            o1[j >> 1] = pack_h2(__float2half_rn(sm32[r * EROWF + i0]),
                                 __float2half_rn(sm32[r * EROWF + i1]));
            o2[j >> 1] = pack_h2(__float2half_rn(sm32[r * EROWF + i0 + 64]),
                                 __float2half_rn(sm32[r * EROWF + i1 + 64]));
        }
#pragma unroll
        for (int j = 0; j < 16; j++) {
            ((uint32_t*)(dst + g))[j]      = o1[j];
            ((uint32_t*)(dst + g + 64))[j] = o2[j];
        }
    }
}

// fp32-output GEMM (output projection) — standard epilogue
__global__ __launch_bounds__(256, 2) void gemm_f16(
    const __half* __restrict__ A, const __half* __restrict__ B,
    float* __restrict__ C, int M, int N, int K, float outscale)
{
    extern __shared__ char smem[];
    const uint32_t sbase = smem_to_u32(smem);
    const int tid  = threadIdx.x;
    const int wid  = tid >> 5;
    const int lane = tid & 31;
    const int wm   = wid >> 2;
    const int wn   = wid & 3;
    const int bm   = blockIdx.y * 128;
    const int bn   = blockIdx.x * 128;
    const int NKT  = K / 32;
    const int cr0 = tid >> 2, cc0 = (tid & 3) * 16;
    const int cr1 = (tid + 256) >> 2;

    GEMM_MAIN();

    const int erow = bm + wm * 64 + (lane >> 2);
    const int ecol = bn + wn * 32 + (lane & 3) * 2;
#pragma unroll
    for (int mf = 0; mf < 4; mf++)
#pragma unroll
        for (int nf = 0; nf < 4; nf++) {
            float* c = acc[mf][nf];
            size_t ro0 = (size_t)(erow + mf * 16) * N + ecol + nf * 8;
            size_t ro1 = ro0 + 8 * (size_t)N;
            *(float2*)(C + ro0) = make_float2(c[0] * outscale, c[1] * outscale);
            *(float2*)(C + ro1) = make_float2(c[2] * outscale, c[3] * outscale);
        }
}
#undef G_ISSUE

// ---------------------------------------------------------------------------
// Split-KV tensor-core flash attention (partial pass) — R14 structure.
// ---------------------------------------------------------------------------
#define FROWB 272
#define FQT   (128 * FROWB)            // 34816
#define FKT   (64 * FROWB)             // 17408
#define FKVST (2 * FKT)                // 34816 per stage
#define FLASH_SMEM (FQT + 2 * FKVST)   // 104448
#define SC_LOG2E 0.12751631762078975f  // (1/sqrt(128)) * log2(e)

__global__ __launch_bounds__(256, 2) void flash_part(
    const __half* __restrict__ C16, __half* __restrict__ Op,
    float2* __restrict__ ml)
{
    extern __shared__ char sm[];
    const uint32_t sb  = smem_to_u32(sm);
    const uint32_t sQ  = sb;
    const uint32_t sKV = sb + FQT;

    const int qi   = blockIdx.x >> 1;
    const int half = blockIdx.x & 1;
    const int qt   = NQ - 1 - qi;        // heaviest first
    const int q0   = qt * 128;
    const int h    = blockIdx.y;
    const int b    = blockIdx.z;
    const int kvh  = h >> 2;
    const int tid  = threadIdx.x;
    const int wid  = tid >> 5;
    const int lane = tid & 31;

    const int ntF = 2 * qt + 2;
    const int t0  = half ? ntF / 2 : 0;
    const int t1  = half ? ntF : ntF / 2;

    const __half* Kp = C16 + QDIM + kvh * HD;
    const __half* Vp = C16 + QDIM + KVDIM + kvh * HD;
    __half* Oph = Op + (size_t)half * MTOK * QDIM;
    float2* mlh = ml + (size_t)half * MTOK * NH;

#define KV_ISSUE(kt, buf) do { \
    uint32_t db = sKV + (uint32_t)(buf) * FKVST; \
    size_t gb = (size_t)(b * SS + (kt)) * QKVD; \
    _Pragma("unroll") \
    for (int j = 0; j < 4; j++) { \
        int i = tid + j * 256; \
        int rr = i >> 4, c16v = (i & 15) * 16; \
        size_t roff = gb + (size_t)rr * QKVD + (c16v >> 1); \
        cp16(db + rr * FROWB + c16v, Kp + roff); \
        cp16(db + FKT + rr * FROWB + c16v, Vp + roff); \
    } \
} while (0)

    KV_ISSUE(t0 * 64, t0 & 1); CP_COMMIT();
    if (t0 + 1 < t1) { KV_ISSUE((t0 + 1) * 64, (t0 + 1) & 1); CP_COMMIT(); }

    for (int i = tid; i < 128 * 16; i += 256) {
        int rr = i >> 4, c = i & 15;
        size_t g = (size_t)(b * SS + q0 + rr) * QKVD + h * HD + c * 8;
        *(uint4*)(sm + rr * FROWB + c * 16) = *(const uint4*)(C16 + g);
    }

    const uint32_t a_off  = (uint32_t)((16 * wid + (lane & 7) + 8 * ((lane >> 3) & 1)) * FROWB
                                       + (lane >> 4) * 16);
    const uint32_t vt_off = (uint32_t)(((lane & 7) + 8 * ((lane >> 3) & 1)) * FROWB
                                       + (lane >> 4) * 16);
    const uint32_t b_off  = (uint32_t)(((lane & 7) + 8 * (lane >> 4)) * FROWB
                                       + ((lane >> 3) & 1) * 16);

    float o[16][4];
#pragma unroll
    for (int nf = 0; nf < 16; nf++)
#pragma unroll
        for (int r = 0; r < 4; r++) o[nf][r] = 0.f;
    float mo[2] = {-1e30f, -1e30f};
    float ls[2] = {0.f, 0.f};

    for (int t = t0; t < t1; t++) {
        const int kt = t * 64;
        if (t + 1 < t1) CP_WAIT(1); else CP_WAIT(0);
        __syncthreads();

        const uint32_t kvb = sKV + (uint32_t)(t & 1) * FKVST;
        const uint32_t cK = kvb, cV = kvb + FKT;

        float s[8][4];
#pragma unroll
        for (int f = 0; f < 8; f++)
#pragma unroll
            for (int r = 0; r < 4; r++) s[f][r] = 0.f;

#pragma unroll
        for (int ks = 0; ks < 8; ks++) {
            uint32_t qq[4];
            LDMX4(qq, sQ + a_off + ks * 32);
#pragma unroll
            for (int nb = 0; nb < 4; nb++) {
                uint32_t kk[4];
                LDMX4(kk, cK + b_off + nb * 16 * FROWB + ks * 32);
                MMA_F16(s[2 * nb],     qq, kk[0], kk[1]);
                MMA_F16(s[2 * nb + 1], qq, kk[2], kk[3]);
            }
        }

#pragma unroll
        for (int f = 0; f < 8; f++)
#pragma unroll
            for (int r = 0; r < 4; r++) s[f][r] *= SC_LOG2E;

        if (t >= ntF - 2) {
            const int row0 = q0 + 16 * wid + (lane >> 2);
            const int colb = kt + 2 * (lane & 3);
#pragma unroll
            for (int f = 0; f < 8; f++)
#pragma unroll
                for (int r = 0; r < 4; r++) {
                    int col = colb + 8 * f + (r & 1);
                    int row = row0 + 8 * (r >> 1);
                    if (col > row) s[f][r] = -1e30f;
                }
        }

#pragma unroll
        for (int hh = 0; hh < 2; hh++) {
            float mt = -1e30f;
#pragma unroll
            for (int f = 0; f < 8; f++)
                mt = fmaxf(mt, fmaxf(s[f][2 * hh], s[f][2 * hh + 1]));
            mt = fmaxf(mt, __shfl_xor_sync(0xffffffffu, mt, 1));
            mt = fmaxf(mt, __shfl_xor_sync(0xffffffffu, mt, 2));
            float mn = fmaxf(mo[hh], mt);
            float rs = 0.f;
#pragma unroll
            for (int f = 0; f < 8; f++) {
                float p0 = exp2f(s[f][2 * hh] - mn);
                float p1 = exp2f(s[f][2 * hh + 1] - mn);
                s[f][2 * hh] = p0;
                s[f][2 * hh + 1] = p1;
                rs += p0 + p1;
            }
            rs += __shfl_xor_sync(0xffffffffu, rs, 1);
            rs += __shfl_xor_sync(0xffffffffu, rs, 2);
            if (mt > mo[hh]) {
                float alpha = exp2f(mo[hh] - mn);
                ls[hh] = ls[hh] * alpha + rs;
                mo[hh] = mn;
#pragma unroll
                for (int nf = 0; nf < 16; nf++) {
                    o[nf][2 * hh]     *= alpha;
                    o[nf][2 * hh + 1] *= alpha;
                }
            } else {
                ls[hh] += rs;
            }
        }

#pragma unroll
        for (int ks = 0; ks < 4; ks++) {
            uint32_t ph[4];
            ph[0] = pack_h2(__float2half_rn(s[2 * ks][0]),     __float2half_rn(s[2 * ks][1]));
            ph[1] = pack_h2(__float2half_rn(s[2 * ks][2]),     __float2half_rn(s[2 * ks][3]));
            ph[2] = pack_h2(__float2half_rn(s[2 * ks + 1][0]), __float2half_rn(s[2 * ks + 1][1]));
            ph[3] = pack_h2(__float2half_rn(s[2 * ks + 1][2]), __float2half_rn(s[2 * ks + 1][3]));
#pragma unroll
            for (int nb = 0; nb < 8; nb++) {
                uint32_t vv[4];
                LDMX4T(vv, cV + vt_off + ks * 16 * FROWB + nb * 32);
                MMA_F16(o[2 * nb],     ph, vv[0], vv[1]);
                MMA_F16(o[2 * nb + 1], ph, vv[2], vv[3]);
            }
        }

        __syncthreads();
        if (t + 2 < t1) { KV_ISSUE((t + 2) * 64, t & 1); CP_COMMIT(); }
    }

    float inv0 = ls[0] > 0.f ? 1.f / ls[0] : 0.f;
    float inv1 = ls[1] > 0.f ? 1.f / ls[1] : 0.f;
#pragma unroll
    for (int nf = 0; nf < 16; nf++) {
#pragma unroll
        for (int rp = 0; rp < 2; rp++) {
            float invv = rp ? inv1 : inv0;
            float v0 = o[nf][2 * rp] * invv;
            float v1 = o[nf][2 * rp + 1] * invv;
            uint32_t hv = pack_h2(__float2half_rn(v0), __float2half_rn(v1));
            int row = q0 + 16 * wid + (lane >> 2) + 8 * rp;
            int col = h * HD + 8 * nf + 2 * (lane & 3);
            size_t g = (size_t)(b * SS + row) * QDIM + col;
            *(uint32_t*)(Oph + g) = hv;
        }
    }
    if ((lane & 3) == 0) {
#pragma unroll
        for (int rp = 0; rp < 2; rp++) {
            int row = q0 + 16 * wid + (lane >> 2) + 8 * rp;
            mlh[(size_t)(b * SS + row) * NH + h] = make_float2(mo[rp], ls[rp]);
        }
    }
#undef KV_ISSUE
}

// ---------------------------------------------------------------------------
// Split-KV combine: O = (w0*O0 + w1*O1)/(w0+w1), w_i = l_i * 2^(m_i - M)
// ---------------------------------------------------------------------------
__global__ void flash_combine(const __half* __restrict__ Op,
                              const float2* __restrict__ ml,
                              __half* __restrict__ O)
{
    int idx = blockIdx.x * blockDim.x + threadIdx.x;
    if (idx >= MTOK * NH * 16) return;
    int cg = idx & 15;
    int rh = idx >> 4;
    int h  = rh & (NH - 1);
    int m  = rh >> 4;

    float2 ml0 = ml[rh];
    float2 ml1 = ml[(size_t)MTOK * NH + rh];
    float M = fmaxf(ml0.x, ml1.x);
    float w0 = ml0.y * exp2f(ml0.x - M);
    float w1 = ml1.y * exp2f(ml1.x - M);
    float inv = 1.f / (w0 + w1);
    w0 *= inv; w1 *= inv;

    size_t off = ((size_t)m * QDIM + h * HD + cg * 8) >> 3;
    uint4 a = ((const uint4*)Op)[off];
    uint4 bq = ((const uint4*)(Op + (size_t)MTOK * QDIM))[off];

    uint4 r;
    uint32_t* ap = (uint32_t*)&a;
    uint32_t* bp = (uint32_t*)&bq;
    uint32_t* rp = (uint32_t*)&r;
#pragma unroll
    for (int j = 0; j < 4; j++) {
        __half2 ha = *(__half2*)&ap[j];
        __half2 hb = *(__half2*)&bp[j];
        float2 fa = __half22float2(ha);
        float2 fb = __half22float2(hb);
        rp[j] = pack_h2(__float2half_rn(fa.x * w0 + fb.x * w1),
                        __float2half_rn(fa.y * w0 + fb.y * w1));
    }
    ((uint4*)O)[off] = r;
}

// ---------------------------------------------------------------------------
// launcher
// ---------------------------------------------------------------------------
extern "C" void kernel_launch(void* const* d_in, const int* in_sizes, int n_in,
                              void* d_out, int out_size)
{
    const float* hidden = (const float*)d_in[0];
    const float* Wq     = (const float*)d_in[1];
    const float* Wk     = (const float*)d_in[2];
    const float* Wv     = (const float*)d_in[3];
    const float* Wo     = (const float*)d_in[4];
    const int*   pos    = (const int*)d_in[5];
    float* out = (float*)d_out;

    __half *C16, *H16, *W16, *Wo16, *O16, *Op;
    float2 *ml, *cs;
    cudaGetSymbolAddress((void**)&C16, g_C16);
    cudaGetSymbolAddress((void**)&H16, g_H16);
    cudaGetSymbolAddress((void**)&W16, g_W16);
    cudaGetSymbolAddress((void**)&Wo16, g_Wo16);
    cudaGetSymbolAddress((void**)&O16, g_O16);
    cudaGetSymbolAddress((void**)&Op, g_Op);
    cudaGetSymbolAddress((void**)&ml, g_ml);
    cudaGetSymbolAddress((void**)&cs, g_cs);

    cudaFuncSetAttribute(gemm_qkv,
                         cudaFuncAttributeMaxDynamicSharedMemorySize, GEMM_SMEM);
    cudaFuncSetAttribute(gemm_f16,
                         cudaFuncAttributeMaxDynamicSharedMemorySize, GEMM_SMEM);
    cudaFuncSetAttribute(flash_part,
                         cudaFuncAttributeMaxDynamicSharedMemorySize, FLASH_SMEM);

    // 1. conversions + rope table, one launch
    conv_all<<<(CALL + 255) / 256, 256>>>(hidden, Wq, Wk, Wv, Wo, H16, W16, Wo16, cs);

    // 2. fused QKV projection with rope epilogue -> fp16 C16 (unscale by 1/64)
    gemm_qkv<<<dim3(QKVD / 128, MTOK / 128), 256, GEMM_SMEM>>>(
        H16, W16, C16, MTOK, QKVD, HID, INV_WSCALE, pos, cs);

    // 3. split-KV flash attention partials + combine
    flash_part<<<dim3(NQ * 2, NH, BB), 256, FLASH_SMEM>>>(C16, Op, ml);
    flash_combine<<<(MTOK * NH * 16 + 255) / 256, 256>>>(Op, ml, O16);

    // 4. output projection (unscale by 1/64)
    gemm_f16<<<dim3(HID / 128, MTOK / 128), 256, GEMM_SMEM>>>(
        O16, Wo16, out, MTOK, HID, QDIM, INV_WSCALE);
}

// round 16
// speedup vs baseline: 1.0574x; 1.0574x over previous
#include <cuda_runtime.h>
#include <cuda_fp16.h>
#include <math.h>
#include <stdint.h>

// Problem constants
#define BB   2
#define SS   2048
#define HID  2048
#define NH   16
#define NKV  4
#define HD   128
#define MTOK (BB*SS)          // 4096
#define QDIM (NH*HD)          // 2048
#define KVDIM (NKV*HD)        // 512
#define QKVD (QDIM + 2*KVDIM) // 3072
#define NQ   (SS/128)         // 16 q-tiles per (b)

#define WSCALE    64.0f
#define INV_WSCALE 0.015625f

// ---------------------------------------------------------------------------
// Scratch (device globals; no allocation allowed)
// ---------------------------------------------------------------------------
__device__ __half g_C16[(size_t)MTOK * QKVD];              // fused QKV fp16 (roped in place)
__device__ __half g_H16[(size_t)MTOK * HID];               // hidden fp16
__device__ __half g_W16[(size_t)QKVD * HID];               // packed QKV weights x64
__device__ __half g_Wo16[(size_t)HID * QDIM];              // Wo x64
__device__ __half g_O16[(size_t)MTOK * QDIM];              // combined attn out fp16
__device__ __half g_Op[2 * (size_t)MTOK * QDIM];           // split-KV partial O (normalized)
__device__ float2 g_ml[2 * (size_t)MTOK * NH];             // split-KV partial (m, l)
__device__ float2 g_cs[(size_t)SS * 64];                   // rope (cos,sin) table [pos][i]

// ---------------------------------------------------------------------------
// helpers
// ---------------------------------------------------------------------------
__device__ __forceinline__ uint32_t smem_to_u32(const void* p) {
    uint32_t a;
    asm("{ .reg .u64 t; cvta.to.shared.u64 t, %1; cvt.u32.u64 %0, t; }"
        : "=r"(a) : "l"(p));
    return a;
}
__device__ __forceinline__ uint32_t pack_h2(__half a, __half b) {
    return (uint32_t)__half_as_ushort(a) | ((uint32_t)__half_as_ushort(b) << 16);
}

#define LDMX4(r, addr) \
    asm volatile("ldmatrix.sync.aligned.m8n8.x4.shared.b16 {%0,%1,%2,%3}, [%4];" \
        : "=r"((r)[0]), "=r"((r)[1]), "=r"((r)[2]), "=r"((r)[3]) : "r"(addr))
#define LDMX4T(r, addr) \
    asm volatile("ldmatrix.sync.aligned.m8n8.x4.trans.shared.b16 {%0,%1,%2,%3}, [%4];" \
        : "=r"((r)[0]), "=r"((r)[1]), "=r"((r)[2]), "=r"((r)[3]) : "r"(addr))
#define MMA_F16(c, a, b0, b1) \
    asm volatile("mma.sync.aligned.m16n8k16.row.col.f32.f16.f16.f32 " \
        "{%0,%1,%2,%3},{%4,%5,%6,%7},{%8,%9},{%0,%1,%2,%3};" \
        : "+f"((c)[0]), "+f"((c)[1]), "+f"((c)[2]), "+f"((c)[3]) \
        : "r"((a)[0]), "r"((a)[1]), "r"((a)[2]), "r"((a)[3]), "r"(b0), "r"(b1))

__device__ __forceinline__ void cp16(uint32_t dst, const void* src) {
    asm volatile("cp.async.cg.shared.global [%0], [%1], 16;" :: "r"(dst), "l"(src));
}
#define CP_COMMIT() asm volatile("cp.async.commit_group;" ::: "memory")
#define CP_WAIT(n)  asm volatile("cp.async.wait_group %0;" :: "n"(n) : "memory")

// ---------------------------------------------------------------------------
// conversion kernel: all fp32 -> fp16 inputs + rope (cos,sin) table build
// ---------------------------------------------------------------------------
#define CN0 (MTOK * HID / 4)     // hidden
#define CN1 (QDIM * HID / 4)     // Wq
#define CN2 (KVDIM * HID / 4)    // Wk
#define CN3 (KVDIM * HID / 4)    // Wv
#define CN4 (HID * QDIM / 4)     // Wo
#define CNT (CN0 + CN1 + CN2 + CN3 + CN4)
#define CTBL (SS * 64)           // rope table entries
#define CALL (CNT + CTBL)

__global__ void conv_all(const float* __restrict__ hid, const float* __restrict__ wq,
                         const float* __restrict__ wk, const float* __restrict__ wv,
                         const float* __restrict__ wo,
                         __half* __restrict__ H16, __half* __restrict__ W16,
                         __half* __restrict__ Wo16, float2* __restrict__ cs)
{
    int i = blockIdx.x * blockDim.x + threadIdx.x;
    if (i >= CALL) return;
    if (i >= CNT) {
        int idx = i - CNT;
        int pos = idx >> 6;
        int ii  = idx & 63;
        double invf = exp(-(double)ii * 0.14391156831212787);  // ln(10000)/64
        double ang = (double)pos * invf;
        double k = rint(ang * 0.15915494309189535);
        float r = (float)(ang - k * 6.283185307179586477);
        float sv, cv;
        sincosf(r, &sv, &cv);
        cs[idx] = make_float2(cv, sv);
        return;
    }
    const float* src;
    __half* dst;
    int j;
    float sc;
    if (i < CN0)                 { src = hid; dst = H16; j = i; sc = 1.f; }
    else if (i < CN0 + CN1)      { src = wq;  dst = W16; j = i - CN0; sc = WSCALE; }
    else if (i < CN0 + CN1 + CN2){ src = wk;  dst = W16 + (size_t)QDIM * HID;
                                   j = i - CN0 - CN1; sc = WSCALE; }
    else if (i < CN0 + CN1 + CN2 + CN3)
                                 { src = wv;  dst = W16 + (size_t)(QDIM + KVDIM) * HID;
                                   j = i - CN0 - CN1 - CN2; sc = WSCALE; }
    else                         { src = wo;  dst = Wo16;
                                   j = i - CN0 - CN1 - CN2 - CN3; sc = WSCALE; }
    float4 v = ((const float4*)src)[j];
    ((uint2*)dst)[j] = make_uint2(
        pack_h2(__float2half_rn(v.x * sc), __float2half_rn(v.y * sc)),
        pack_h2(__float2half_rn(v.z * sc), __float2half_rn(v.w * sc)));
}

// ---------------------------------------------------------------------------
// RoPE in-place on fp16 C16 using the precomputed cs table (bandwidth-bound).
// Q region (16 heads) + K region (4 heads), one launch.
// ---------------------------------------------------------------------------
__global__ void rope_all(__half* __restrict__ C, const int* __restrict__ pos_ids,
                         const float2* __restrict__ cs)
{
    int idx = blockIdx.x * blockDim.x + threadIdx.x;
    if (idx >= 2 * MTOK * 64) return;
    int nheads, colbase;
    if (idx < MTOK * 64) { nheads = NH;  colbase = 0; }
    else                 { nheads = NKV; colbase = QDIM; idx -= MTOK * 64; }
    int i = idx & 63;
    int m = idx >> 6;
    float2 cspair = cs[((size_t)pos_ids[m] << 6) + i];
    float cv = cspair.x, sv = cspair.y;

    size_t base = (size_t)m * QKVD + colbase + i;
#pragma unroll 4
    for (int h = 0; h < nheads; h++) {
        float x1 = __half2float(C[base]);
        float x2 = __half2float(C[base + 64]);
        C[base]      = __float2half_rn(x1 * cv - x2 * sv);
        C[base + 64] = __float2half_rn(x2 * cv + x1 * sv);
        base += 128;
    }
}

// ---------------------------------------------------------------------------
// GEMM core: CTA 128x128, BK=32, 256 thr, 8 warps (warp 64x32).
// 4-stage cp.async pipeline, one __syncthreads per K-iteration.
// ---------------------------------------------------------------------------
#define SROW   40
#define TPART  (128 * SROW * 2)        // 10240 B
#define TSTAGE (2 * TPART)             // 20480 B
#define GEMM_SMEM (4 * TSTAGE)         // 81920 B

#define GEMM_COMPUTE(kt) do { \
    const uint32_t base_ = sbase + (uint32_t)((kt) & 3) * TSTAGE; \
    _Pragma("unroll") \
    for (int ks = 0; ks < 2; ks++) { \
        const uint32_t kb = ks * 32; \
        uint32_t ah[4][4], bh2[2][4]; \
        _Pragma("unroll") \
        for (int mf = 0; mf < 4; mf++) \
            LDMX4(ah[mf], base_ + a_lane + mf * 16 * (SROW * 2) + kb); \
        _Pragma("unroll") \
        for (int nf2 = 0; nf2 < 2; nf2++) \
            LDMX4(bh2[nf2], base_ + TPART + b_lane + nf2 * 16 * (SROW * 2) + kb); \
        _Pragma("unroll") \
        for (int mf = 0; mf < 4; mf++) \
            _Pragma("unroll") \
            for (int nf = 0; nf < 4; nf++) \
                MMA_F16(acc[mf][nf], ah[mf], \
                        bh2[nf >> 1][nf & 1], bh2[nf >> 1][(nf & 1) + 2]); \
    } \
} while (0)

#define GEMM_BODY(EPILOGUE) \
    extern __shared__ char smem[]; \
    const uint32_t sbase = smem_to_u32(smem); \
    const int tid  = threadIdx.x; \
    const int wid  = tid >> 5; \
    const int lane = tid & 31; \
    const int wm   = wid >> 2; \
    const int wn   = wid & 3; \
    const int bm   = blockIdx.y * 128; \
    const int bn   = blockIdx.x * 128; \
    const int NKT  = K / 32; \
    const int cr0 = tid >> 2, cc0 = (tid & 3) * 16; \
    const int cr1 = (tid + 256) >> 2; \
    float acc[4][4][4]; \
    _Pragma("unroll") \
    for (int mf = 0; mf < 4; mf++) \
        _Pragma("unroll") \
        for (int nf = 0; nf < 4; nf++) \
            _Pragma("unroll") \
            for (int r = 0; r < 4; r++) acc[mf][nf][r] = 0.f; \
    G_ISSUE(0, 0); CP_COMMIT(); \
    G_ISSUE(1, 1); CP_COMMIT(); \
    G_ISSUE(2, 2); CP_COMMIT(); \
    const int lr16 = lane & 15; \
    const int lh   = lane >> 4; \
    const uint32_t a_lane = (uint32_t)((wm * 64 + lr16) * (SROW * 2) + lh * 16); \
    const uint32_t b_lane = (uint32_t)((wn * 32 + lr16) * (SROW * 2) + lh * 16); \
    for (int kt = 0; kt < NKT; kt++) { \
        if (kt + 3 <= NKT)       CP_WAIT(2); \
        else if (kt + 2 == NKT)  CP_WAIT(1); \
        else                     CP_WAIT(0); \
        __syncthreads(); \
        if (kt + 3 < NKT) { G_ISSUE(kt + 3, (kt + 3) & 3); CP_COMMIT(); } \
        GEMM_COMPUTE(kt); \
    } \
    const int erow = bm + wm * 64 + (lane >> 2); \
    const int ecol = bn + wn * 32 + (lane & 3) * 2; \
    EPILOGUE

#define G_ISSUE(kt, buf) do { \
    uint32_t db = sbase + (uint32_t)(buf) * TSTAGE; \
    cp16(db + cr0 * 80 + cc0, \
         A + (size_t)(bm + cr0) * K + (kt) * 32 + (cc0 >> 1)); \
    cp16(db + cr1 * 80 + cc0, \
         A + (size_t)(bm + cr1) * K + (kt) * 32 + (cc0 >> 1)); \
    cp16(db + TPART + cr0 * 80 + cc0, \
         B + (size_t)(bn + cr0) * K + (kt) * 32 + (cc0 >> 1)); \
    cp16(db + TPART + cr1 * 80 + cc0, \
         B + (size_t)(bn + cr1) * K + (kt) * 32 + (cc0 >> 1)); \
} while (0)

// fp16-output GEMM (QKV projection)
__global__ __launch_bounds__(256, 2) void gemm_f16h(
    const __half* __restrict__ A, const __half* __restrict__ B,
    __half* __restrict__ C, int M, int N, int K, float outscale)
{
    GEMM_BODY(
#pragma unroll
        for (int mf = 0; mf < 4; mf++)
#pragma unroll
            for (int nf = 0; nf < 4; nf++) {
                float* c = acc[mf][nf];
                size_t ro0 = (size_t)(erow + mf * 16) * N + ecol + nf * 8;
                size_t ro1 = ro0 + 8 * (size_t)N;
                *(uint32_t*)(C + ro0) = pack_h2(
                    __float2half_rn(c[0] * outscale), __float2half_rn(c[1] * outscale));
                *(uint32_t*)(C + ro1) = pack_h2(
                    __float2half_rn(c[2] * outscale), __float2half_rn(c[3] * outscale));
            }
    )
}

// fp32-output GEMM (output projection)
__global__ __launch_bounds__(256, 2) void gemm_f16(
    const __half* __restrict__ A, const __half* __restrict__ B,
    float* __restrict__ C, int M, int N, int K, float outscale)
{
    GEMM_BODY(
#pragma unroll
        for (int mf = 0; mf < 4; mf++)
#pragma unroll
            for (int nf = 0; nf < 4; nf++) {
                float* c = acc[mf][nf];
                size_t ro0 = (size_t)(erow + mf * 16) * N + ecol + nf * 8;
                size_t ro1 = ro0 + 8 * (size_t)N;
                *(float2*)(C + ro0) = make_float2(c[0] * outscale, c[1] * outscale);
                *(float2*)(C + ro1) = make_float2(c[2] * outscale, c[3] * outscale);
            }
    )
}
#undef G_ISSUE

// ---------------------------------------------------------------------------
// Split-KV tensor-core flash attention (partial pass).
// KV cp.async issued BEFORE the synchronous Q load so they overlap.
// ---------------------------------------------------------------------------
#define FROWB 272
#define FQT   (128 * FROWB)            // 34816
#define FKT   (64 * FROWB)             // 17408
#define FKVST (2 * FKT)                // 34816 per stage
#define FLASH_SMEM (FQT + 2 * FKVST)   // 104448
#define SC_LOG2E 0.12751631762078975f  // (1/sqrt(128)) * log2(e)

__global__ __launch_bounds__(256, 2) void flash_part(
    const __half* __restrict__ C16, __half* __restrict__ Op,
    float2* __restrict__ ml)
{
    extern __shared__ char sm[];
    const uint32_t sb  = smem_to_u32(sm);
    const uint32_t sQ  = sb;
    const uint32_t sKV = sb + FQT;

    const int qi   = blockIdx.x >> 1;
    const int half = blockIdx.x & 1;
    const int qt   = NQ - 1 - qi;        // heaviest first
    const int q0   = qt * 128;
    const int h    = blockIdx.y;
    const int b    = blockIdx.z;
    const int kvh  = h >> 2;
    const int tid  = threadIdx.x;
    const int wid  = tid >> 5;
    const int lane = tid & 31;

    const int ntF = 2 * qt + 2;
    const int t0  = half ? ntF / 2 : 0;
    const int t1  = half ? ntF : ntF / 2;

    const __half* Kp = C16 + QDIM + kvh * HD;
    const __half* Vp = C16 + QDIM + KVDIM + kvh * HD;
    __half* Oph = Op + (size_t)half * MTOK * QDIM;
    float2* mlh = ml + (size_t)half * MTOK * NH;

#define KV_ISSUE(kt, buf) do { \
    uint32_t db = sKV + (uint32_t)(buf) * FKVST; \
    size_t gb = (size_t)(b * SS + (kt)) * QKVD; \
    _Pragma("unroll") \
    for (int j = 0; j < 4; j++) { \
        int i = tid + j * 256; \
        int rr = i >> 4, c16v = (i & 15) * 16; \
        size_t roff = gb + (size_t)rr * QKVD + (c16v >> 1); \
        cp16(db + rr * FROWB + c16v, Kp + roff); \
        cp16(db + FKT + rr * FROWB + c16v, Vp + roff); \
    } \
} while (0)

    KV_ISSUE(t0 * 64, t0 & 1); CP_COMMIT();
    if (t0 + 1 < t1) { KV_ISSUE((t0 + 1) * 64, (t0 + 1) & 1); CP_COMMIT(); }

    for (int i = tid; i < 128 * 16; i += 256) {
        int rr = i >> 4, c = i & 15;
        size_t g = (size_t)(b * SS + q0 + rr) * QKVD + h * HD + c * 8;
        *(uint4*)(sm + rr * FROWB + c * 16) = *(const uint4*)(C16 + g);
    }

    const uint32_t a_off  = (uint32_t)((16 * wid + (lane & 7) + 8 * ((lane >> 3) & 1)) * FROWB
                                       + (lane >> 4) * 16);
    const uint32_t vt_off = (uint32_t)(((lane & 7) + 8 * ((lane >> 3) & 1)) * FROWB
                                       + (lane >> 4) * 16);
    const uint32_t b_off  = (uint32_t)(((lane & 7) + 8 * (lane >> 4)) * FROWB
                                       + ((lane >> 3) & 1) * 16);

    float o[16][4];
#pragma unroll
    for (int nf = 0; nf < 16; nf++)
#pragma unroll
        for (int r = 0; r < 4; r++) o[nf][r] = 0.f;
    float mo[2] = {-1e30f, -1e30f};
    float ls[2] = {0.f, 0.f};

    for (int t = t0; t < t1; t++) {
        const int kt = t * 64;
        if (t + 1 < t1) CP_WAIT(1); else CP_WAIT(0);
        __syncthreads();

        const uint32_t kvb = sKV + (uint32_t)(t & 1) * FKVST;
        const uint32_t cK = kvb, cV = kvb + FKT;

        float s[8][4];
#pragma unroll
        for (int f = 0; f < 8; f++)
#pragma unroll
            for (int r = 0; r < 4; r++) s[f][r] = 0.f;

#pragma unroll
        for (int ks = 0; ks < 8; ks++) {
            uint32_t qq[4];
            LDMX4(qq, sQ + a_off + ks * 32);
#pragma unroll
            for (int nb = 0; nb < 4; nb++) {
                uint32_t kk[4];
                LDMX4(kk, cK + b_off + nb * 16 * FROWB + ks * 32);
                MMA_F16(s[2 * nb],     qq, kk[0], kk[1]);
                MMA_F16(s[2 * nb + 1], qq, kk[2], kk[3]);
            }
        }

#pragma unroll
        for (int f = 0; f < 8; f++)
#pragma unroll
            for (int r = 0; r < 4; r++) s[f][r] *= SC_LOG2E;

        if (t >= ntF - 2) {
            const int row0 = q0 + 16 * wid + (lane >> 2);
            const int colb = kt + 2 * (lane & 3);
#pragma unroll
            for (int f = 0; f < 8; f++)
#pragma unroll
                for (int r = 0; r < 4; r++) {
                    int col = colb + 8 * f + (r & 1);
                    int row = row0 + 8 * (r >> 1);
                    if (col > row) s[f][r] = -1e30f;
                }
        }

#pragma unroll
        for (int hh = 0; hh < 2; hh++) {
            float mt = -1e30f;
#pragma unroll
            for (int f = 0; f < 8; f++)
                mt = fmaxf(mt, fmaxf(s[f][2 * hh], s[f][2 * hh + 1]));
            mt = fmaxf(mt, __shfl_xor_sync(0xffffffffu, mt, 1));
            mt = fmaxf(mt, __shfl_xor_sync(0xffffffffu, mt, 2));
            float mn = fmaxf(mo[hh], mt);
            float rs = 0.f;
#pragma unroll
            for (int f = 0; f < 8; f++) {
                float p0 = exp2f(s[f][2 * hh] - mn);
                float p1 = exp2f(s[f][2 * hh + 1] - mn);
                s[f][2 * hh] = p0;
                s[f][2 * hh + 1] = p1;
                rs += p0 + p1;
            }
            rs += __shfl_xor_sync(0xffffffffu, rs, 1);
            rs += __shfl_xor_sync(0xffffffffu, rs, 2);
            if (mt > mo[hh]) {
                float alpha = exp2f(mo[hh] - mn);
                ls[hh] = ls[hh] * alpha + rs;
                mo[hh] = mn;
#pragma unroll
                for (int nf = 0; nf < 16; nf++) {
                    o[nf][2 * hh]     *= alpha;
                    o[nf][2 * hh + 1] *= alpha;
                }
            } else {
                ls[hh] += rs;
            }
        }

#pragma unroll
        for (int ks = 0; ks < 4; ks++) {
            uint32_t ph[4];
            ph[0] = pack_h2(__float2half_rn(s[2 * ks][0]),     __float2half_rn(s[2 * ks][1]));
            ph[1] = pack_h2(__float2half_rn(s[2 * ks][2]),     __float2half_rn(s[2 * ks][3]));
            ph[2] = pack_h2(__float2half_rn(s[2 * ks + 1][0]), __float2half_rn(s[2 * ks + 1][1]));
            ph[3] = pack_h2(__float2half_rn(s[2 * ks + 1][2]), __float2half_rn(s[2 * ks + 1][3]));
#pragma unroll
            for (int nb = 0; nb < 8; nb++) {
                uint32_t vv[4];
                LDMX4T(vv, cV + vt_off + ks * 16 * FROWB + nb * 32);
                MMA_F16(o[2 * nb],     ph, vv[0], vv[1]);
                MMA_F16(o[2 * nb + 1], ph, vv[2], vv[3]);
            }
        }

        __syncthreads();
        if (t + 2 < t1) { KV_ISSUE((t + 2) * 64, t & 1); CP_COMMIT(); }
    }

    float inv0 = ls[0] > 0.f ? 1.f / ls[0] : 0.f;
    float inv1 = ls[1] > 0.f ? 1.f / ls[1] : 0.f;
#pragma unroll
    for (int nf = 0; nf < 16; nf++) {
#pragma unroll
        for (int rp = 0; rp < 2; rp++) {
            float invv = rp ? inv1 : inv0;
            float v0 = o[nf][2 * rp] * invv;
            float v1 = o[nf][2 * rp + 1] * invv;
            uint32_t hv = pack_h2(__float2half_rn(v0), __float2half_rn(v1));
            int row = q0 + 16 * wid + (lane >> 2) + 8 * rp;
            int col = h * HD + 8 * nf + 2 * (lane & 3);
            size_t g = (size_t)(b * SS + row) * QDIM + col;
            *(uint32_t*)(Oph + g) = hv;
        }
    }
    if ((lane & 3) == 0) {
#pragma unroll
        for (int rp = 0; rp < 2; rp++) {
            int row = q0 + 16 * wid + (lane >> 2) + 8 * rp;
            mlh[(size_t)(b * SS + row) * NH + h] = make_float2(mo[rp], ls[rp]);
        }
    }
#undef KV_ISSUE
}

// ---------------------------------------------------------------------------
// Split-KV combine: O = (w0*O0 + w1*O1)/(w0+w1), w_i = l_i * 2^(m_i - M)
// ---------------------------------------------------------------------------
__global__ void flash_combine(const __half* __restrict__ Op,
                              const float2* __restrict__ ml,
                              __half* __restrict__ O)
{
    int idx = blockIdx.x * blockDim.x + threadIdx.x;
    if (idx >= MTOK * NH * 16) return;
    int cg = idx & 15;
    int rh = idx >> 4;
    int h  = rh & (NH - 1);
    int m  = rh >> 4;

    float2 ml0 = ml[rh];
    float2 ml1 = ml[(size_t)MTOK * NH + rh];
    float M = fmaxf(ml0.x, ml1.x);
    float w0 = ml0.y * exp2f(ml0.x - M);
    float w1 = ml1.y * exp2f(ml1.x - M);
    float inv = 1.f / (w0 + w1);
    w0 *= inv; w1 *= inv;

    size_t off = ((size_t)m * QDIM + h * HD + cg * 8) >> 3;
    uint4 a = ((const uint4*)Op)[off];
    uint4 bq = ((const uint4*)(Op + (size_t)MTOK * QDIM))[off];

    uint4 r;
    uint32_t* ap = (uint32_t*)&a;
    uint32_t* bp = (uint32_t*)&bq;
    uint32_t* rp = (uint32_t*)&r;
#pragma unroll
    for (int j = 0; j < 4; j++) {
        __half2 ha = *(__half2*)&ap[j];
        __half2 hb = *(__half2*)&bp[j];
        float2 fa = __half22float2(ha);
        float2 fb = __half22float2(hb);
        rp[j] = pack_h2(__float2half_rn(fa.x * w0 + fb.x * w1),
                        __float2half_rn(fa.y * w0 + fb.y * w1));
    }
    ((uint4*)O)[off] = r;
}

// ---------------------------------------------------------------------------
// launcher
// ---------------------------------------------------------------------------
extern "C" void kernel_launch(void* const* d_in, const int* in_sizes, int n_in,
                              void* d_out, int out_size)
{
    const float* hidden = (const float*)d_in[0];
    const float* Wq     = (const float*)d_in[1];
    const float* Wk     = (const float*)d_in[2];
    const float* Wv     = (const float*)d_in[3];
    const float* Wo     = (const float*)d_in[4];
    const int*   pos    = (const int*)d_in[5];
    float* out = (float*)d_out;

    __half *C16, *H16, *W16, *Wo16, *O16, *Op;
    float2 *ml, *cs;
    cudaGetSymbolAddress((void**)&C16, g_C16);
    cudaGetSymbolAddress((void**)&H16, g_H16);
    cudaGetSymbolAddress((void**)&W16, g_W16);
    cudaGetSymbolAddress((void**)&Wo16, g_Wo16);
    cudaGetSymbolAddress((void**)&O16, g_O16);
    cudaGetSymbolAddress((void**)&Op, g_Op);
    cudaGetSymbolAddress((void**)&ml, g_ml);
    cudaGetSymbolAddress((void**)&cs, g_cs);

    cudaFuncSetAttribute(gemm_f16h,
                         cudaFuncAttributeMaxDynamicSharedMemorySize, GEMM_SMEM);
    cudaFuncSetAttribute(gemm_f16,
                         cudaFuncAttributeMaxDynamicSharedMemorySize, GEMM_SMEM);
    cudaFuncSetAttribute(flash_part,
                         cudaFuncAttributeMaxDynamicSharedMemorySize, FLASH_SMEM);

    // 1. conversions + rope table, one launch
    conv_all<<<(CALL + 255) / 256, 256>>>(hidden, Wq, Wk, Wv, Wo, H16, W16, Wo16, cs);

    // 2. fused QKV projection -> fp16 C16 [MTOK, 3072] (unscale by 1/64)
    gemm_f16h<<<dim3(QKVD / 128, MTOK / 128), 256, GEMM_SMEM>>>(
        H16, W16, C16, MTOK, QKVD, HID, INV_WSCALE);

    // 3. RoPE in place on C16 (table-based, one launch)
    rope_all<<<(2 * MTOK * 64 + 255) / 256, 256>>>(C16, pos, cs);

    // 4. split-KV flash attention partials + combine
    flash_part<<<dim3(NQ * 2, NH, BB), 256, FLASH_SMEM>>>(C16, Op, ml);
    flash_combine<<<(MTOK * NH * 16 + 255) / 256, 256>>>(Op, ml, O16);

    // 5. output projection (unscale by 1/64)
    gemm_f16<<<dim3(HID / 128, MTOK / 128), 256, GEMM_SMEM>>>(
        O16, Wo16, out, MTOK, HID, QDIM, INV_WSCALE);
}

// round 17
// speedup vs baseline: 1.0697x; 1.0117x over previous
#include <cuda_runtime.h>
#include <cuda_fp16.h>
#include <math.h>
#include <stdint.h>

// Problem constants
#define BB   2
#define SS   2048
#define HID  2048
#define NH   16
#define NKV  4
#define HD   128
#define MTOK (BB*SS)          // 4096
#define QDIM (NH*HD)          // 2048
#define KVDIM (NKV*HD)        // 512
#define QKVD (QDIM + 2*KVDIM) // 3072
#define NQ   (SS/128)         // 16 q-tiles per (b)

#define WSCALE    64.0f
#define INV_WSCALE 0.015625f

// ---------------------------------------------------------------------------
// Scratch (device globals; no allocation allowed)
// ---------------------------------------------------------------------------
__device__ __half g_C16[(size_t)MTOK * QKVD];              // fused QKV fp16 (roped in place)
__device__ __half g_H16[(size_t)MTOK * HID];               // hidden fp16
__device__ __half g_W16[(size_t)QKVD * HID];               // packed QKV weights x64
__device__ __half g_Wo16[(size_t)HID * QDIM];              // Wo x64
__device__ __half g_O16[(size_t)MTOK * QDIM];              // combined attn out fp16
__device__ __half g_Op[2 * (size_t)MTOK * QDIM];           // split-KV partial O (normalized)
__device__ float2 g_ml[2 * (size_t)MTOK * NH];             // split-KV partial (m, l)
__device__ float2 g_cs[(size_t)SS * 64];                   // rope (cos,sin) table [pos][i]

// ---------------------------------------------------------------------------
// helpers
// ---------------------------------------------------------------------------
__device__ __forceinline__ uint32_t smem_to_u32(const void* p) {
    uint32_t a;
    asm("{ .reg .u64 t; cvta.to.shared.u64 t, %1; cvt.u32.u64 %0, t; }"
        : "=r"(a) : "l"(p));
    return a;
}
__device__ __forceinline__ uint32_t pack_h2(__half a, __half b) {
    return (uint32_t)__half_as_ushort(a) | ((uint32_t)__half_as_ushort(b) << 16);
}

#define LDMX4(r, addr) \
    asm volatile("ldmatrix.sync.aligned.m8n8.x4.shared.b16 {%0,%1,%2,%3}, [%4];" \
        : "=r"((r)[0]), "=r"((r)[1]), "=r"((r)[2]), "=r"((r)[3]) : "r"(addr))
#define LDMX4T(r, addr) \
    asm volatile("ldmatrix.sync.aligned.m8n8.x4.trans.shared.b16 {%0,%1,%2,%3}, [%4];" \
        : "=r"((r)[0]), "=r"((r)[1]), "=r"((r)[2]), "=r"((r)[3]) : "r"(addr))
#define MMA_F16(c, a, b0, b1) \
    asm volatile("mma.sync.aligned.m16n8k16.row.col.f32.f16.f16.f32 " \
        "{%0,%1,%2,%3},{%4,%5,%6,%7},{%8,%9},{%0,%1,%2,%3};" \
        : "+f"((c)[0]), "+f"((c)[1]), "+f"((c)[2]), "+f"((c)[3]) \
        : "r"((a)[0]), "r"((a)[1]), "r"((a)[2]), "r"((a)[3]), "r"(b0), "r"(b1))

__device__ __forceinline__ void cp16(uint32_t dst, const void* src) {
    asm volatile("cp.async.cg.shared.global [%0], [%1], 16;" :: "r"(dst), "l"(src));
}
#define CP_COMMIT() asm volatile("cp.async.commit_group;" ::: "memory")
#define CP_WAIT(n)  asm volatile("cp.async.wait_group %0;" :: "n"(n) : "memory")

// ---------------------------------------------------------------------------
// conversion kernel: all fp32 -> fp16 inputs + rope (cos,sin) table build
// Each thread handles 2 work items (grid-stride) for better ILP.
// ---------------------------------------------------------------------------
#define CN0 (MTOK * HID / 4)     // hidden
#define CN1 (QDIM * HID / 4)     // Wq
#define CN2 (KVDIM * HID / 4)    // Wk
#define CN3 (KVDIM * HID / 4)    // Wv
#define CN4 (HID * QDIM / 4)     // Wo
#define CNT (CN0 + CN1 + CN2 + CN3 + CN4)
#define CTBL (SS * 64)           // rope table entries
#define CALL (CNT + CTBL)
#define CHALF ((CALL + 1) / 2)

__device__ __forceinline__ void conv_one(
    int i, const float* hid, const float* wq, const float* wk,
    const float* wv, const float* wo,
    __half* H16, __half* W16, __half* Wo16, float2* cs)
{
    if (i >= CNT) {
        int idx = i - CNT;
        int pos = idx >> 6;
        int ii  = idx & 63;
        double invf = exp(-(double)ii * 0.14391156831212787);  // ln(10000)/64
        double ang = (double)pos * invf;
        double k = rint(ang * 0.15915494309189535);
        float r = (float)(ang - k * 6.283185307179586477);
        float sv, cv;
        sincosf(r, &sv, &cv);
        cs[idx] = make_float2(cv, sv);
        return;
    }
    const float* src;
    __half* dst;
    int j;
    float sc;
    if (i < CN0)                 { src = hid; dst = H16; j = i; sc = 1.f; }
    else if (i < CN0 + CN1)      { src = wq;  dst = W16; j = i - CN0; sc = WSCALE; }
    else if (i < CN0 + CN1 + CN2){ src = wk;  dst = W16 + (size_t)QDIM * HID;
                                   j = i - CN0 - CN1; sc = WSCALE; }
    else if (i < CN0 + CN1 + CN2 + CN3)
                                 { src = wv;  dst = W16 + (size_t)(QDIM + KVDIM) * HID;
                                   j = i - CN0 - CN1 - CN2; sc = WSCALE; }
    else                         { src = wo;  dst = Wo16;
                                   j = i - CN0 - CN1 - CN2 - CN3; sc = WSCALE; }
    float4 v = ((const float4*)src)[j];
    ((uint2*)dst)[j] = make_uint2(
        pack_h2(__float2half_rn(v.x * sc), __float2half_rn(v.y * sc)),
        pack_h2(__float2half_rn(v.z * sc), __float2half_rn(v.w * sc)));
}

__global__ void conv_all(const float* __restrict__ hid, const float* __restrict__ wq,
                         const float* __restrict__ wk, const float* __restrict__ wv,
                         const float* __restrict__ wo,
                         __half* __restrict__ H16, __half* __restrict__ W16,
                         __half* __restrict__ Wo16, float2* __restrict__ cs)
{
    int i = blockIdx.x * blockDim.x + threadIdx.x;
    if (i < CALL) conv_one(i, hid, wq, wk, wv, wo, H16, W16, Wo16, cs);
    int i2 = i + CHALF;
    if (i2 < CALL) conv_one(i2, hid, wq, wk, wv, wo, H16, W16, Wo16, cs);
}

// ---------------------------------------------------------------------------
// RoPE in-place on fp16 C16 using the precomputed cs table (bandwidth-bound).
// ---------------------------------------------------------------------------
__global__ void rope_all(__half* __restrict__ C, const int* __restrict__ pos_ids,
                         const float2* __restrict__ cs)
{
    int idx = blockIdx.x * blockDim.x + threadIdx.x;
    if (idx >= 2 * MTOK * 64) return;
    int nheads, colbase;
    if (idx < MTOK * 64) { nheads = NH;  colbase = 0; }
    else                 { nheads = NKV; colbase = QDIM; idx -= MTOK * 64; }
    int i = idx & 63;
    int m = idx >> 6;
    float2 cspair = cs[((size_t)pos_ids[m] << 6) + i];
    float cv = cspair.x, sv = cspair.y;

    size_t base = (size_t)m * QKVD + colbase + i;
#pragma unroll 4
    for (int h = 0; h < nheads; h++) {
        float x1 = __half2float(C[base]);
        float x2 = __half2float(C[base + 64]);
        C[base]      = __float2half_rn(x1 * cv - x2 * sv);
        C[base + 64] = __float2half_rn(x2 * cv + x1 * sv);
        base += 128;
    }
}

// ---------------------------------------------------------------------------
// GEMM core: CTA 128x128, BK=32, 256 thr, 8 warps (warp 64x32).
// 4-stage cp.async pipeline, one __syncthreads per K-iteration.
// ---------------------------------------------------------------------------
#define SROW   40
#define TPART  (128 * SROW * 2)        // 10240 B
#define TSTAGE (2 * TPART)             // 20480 B
#define GEMM_SMEM (4 * TSTAGE)         // 81920 B

#define GEMM_COMPUTE(kt) do { \
    const uint32_t base_ = sbase + (uint32_t)((kt) & 3) * TSTAGE; \
    _Pragma("unroll") \
    for (int ks = 0; ks < 2; ks++) { \
        const uint32_t kb = ks * 32; \
        uint32_t ah[4][4], bh2[2][4]; \
        _Pragma("unroll") \
        for (int mf = 0; mf < 4; mf++) \
            LDMX4(ah[mf], base_ + a_lane + mf * 16 * (SROW * 2) + kb); \
        _Pragma("unroll") \
        for (int nf2 = 0; nf2 < 2; nf2++) \
            LDMX4(bh2[nf2], base_ + TPART + b_lane + nf2 * 16 * (SROW * 2) + kb); \
        _Pragma("unroll") \
        for (int mf = 0; mf < 4; mf++) \
            _Pragma("unroll") \
            for (int nf = 0; nf < 4; nf++) \
                MMA_F16(acc[mf][nf], ah[mf], \
                        bh2[nf >> 1][nf & 1], bh2[nf >> 1][(nf & 1) + 2]); \
    } \
} while (0)

#define GEMM_BODY(EPILOGUE) \
    extern __shared__ char smem[]; \
    const uint32_t sbase = smem_to_u32(smem); \
    const int tid  = threadIdx.x; \
    const int wid  = tid >> 5; \
    const int lane = tid & 31; \
    const int wm   = wid >> 2; \
    const int wn   = wid & 3; \
    const int bm   = blockIdx.y * 128; \
    const int bn   = blockIdx.x * 128; \
    const int NKT  = K / 32; \
    const int cr0 = tid >> 2, cc0 = (tid & 3) * 16; \
    const int cr1 = (tid + 256) >> 2; \
    float acc[4][4][4]; \
    _Pragma("unroll") \
    for (int mf = 0; mf < 4; mf++) \
        _Pragma("unroll") \
        for (int nf = 0; nf < 4; nf++) \
            _Pragma("unroll") \
            for (int r = 0; r < 4; r++) acc[mf][nf][r] = 0.f; \
    G_ISSUE(0, 0); CP_COMMIT(); \
    G_ISSUE(1, 1); CP_COMMIT(); \
    G_ISSUE(2, 2); CP_COMMIT(); \
    const int lr16 = lane & 15; \
    const int lh   = lane >> 4; \
    const uint32_t a_lane = (uint32_t)((wm * 64 + lr16) * (SROW * 2) + lh * 16); \
    const uint32_t b_lane = (uint32_t)((wn * 32 + lr16) * (SROW * 2) + lh * 16); \
    for (int kt = 0; kt < NKT; kt++) { \
        if (kt + 3 <= NKT)       CP_WAIT(2); \
        else if (kt + 2 == NKT)  CP_WAIT(1); \
        else                     CP_WAIT(0); \
        __syncthreads(); \
        if (kt + 3 < NKT) { G_ISSUE(kt + 3, (kt + 3) & 3); CP_COMMIT(); } \
        GEMM_COMPUTE(kt); \
    } \
    const int erow = bm + wm * 64 + (lane >> 2); \
    const int ecol = bn + wn * 32 + (lane & 3) * 2; \
    EPILOGUE

#define G_ISSUE(kt, buf) do { \
    uint32_t db = sbase + (uint32_t)(buf) * TSTAGE; \
    cp16(db + cr0 * 80 + cc0, \
         A + (size_t)(bm + cr0) * K + (kt) * 32 + (cc0 >> 1)); \
    cp16(db + cr1 * 80 + cc0, \
         A + (size_t)(bm + cr1) * K + (kt) * 32 + (cc0 >> 1)); \
    cp16(db + TPART + cr0 * 80 + cc0, \
         B + (size_t)(bn + cr0) * K + (kt) * 32 + (cc0 >> 1)); \
    cp16(db + TPART + cr1 * 80 + cc0, \
         B + (size_t)(bn + cr1) * K + (kt) * 32 + (cc0 >> 1)); \
} while (0)

// fp16-output GEMM (QKV projection)
__global__ __launch_bounds__(256, 2) void gemm_f16h(
    const __half* __restrict__ A, const __half* __restrict__ B,
    __half* __restrict__ C, int M, int N, int K, float outscale)
{
    GEMM_BODY(
#pragma unroll
        for (int mf = 0; mf < 4; mf++)
#pragma unroll
            for (int nf = 0; nf < 4; nf++) {
                float* c = acc[mf][nf];
                size_t ro0 = (size_t)(erow + mf * 16) * N + ecol + nf * 8;
                size_t ro1 = ro0 + 8 * (size_t)N;
                *(uint32_t*)(C + ro0) = pack_h2(
                    __float2half_rn(c[0] * outscale), __float2half_rn(c[1] * outscale));
                *(uint32_t*)(C + ro1) = pack_h2(
                    __float2half_rn(c[2] * outscale), __float2half_rn(c[3] * outscale));
            }
    )
}

// fp32-output GEMM (output projection)
__global__ __launch_bounds__(256, 2) void gemm_f16(
    const __half* __restrict__ A, const __half* __restrict__ B,
    float* __restrict__ C, int M, int N, int K, float outscale)
{
    GEMM_BODY(
#pragma unroll
        for (int mf = 0; mf < 4; mf++)
#pragma unroll
            for (int nf = 0; nf < 4; nf++) {
                float* c = acc[mf][nf];
                size_t ro0 = (size_t)(erow + mf * 16) * N + ecol + nf * 8;
                size_t ro1 = ro0 + 8 * (size_t)N;
                *(float2*)(C + ro0) = make_float2(c[0] * outscale, c[1] * outscale);
                *(float2*)(C + ro1) = make_float2(c[2] * outscale, c[3] * outscale);
            }
    )
}
#undef G_ISSUE

// ---------------------------------------------------------------------------
// Split-KV tensor-core flash attention (partial pass).
// Q tile loaded via cp.async (commit group 0) so it overlaps the KV groups;
// the existing CP_WAIT(1) before the first tile covers Q + KV0 completion.
// ---------------------------------------------------------------------------
#define FROWB 272
#define FQT   (128 * FROWB)            // 34816
#define FKT   (64 * FROWB)             // 17408
#define FKVST (2 * FKT)                // 34816 per stage
#define FLASH_SMEM (FQT + 2 * FKVST)   // 104448
#define SC_LOG2E 0.12751631762078975f  // (1/sqrt(128)) * log2(e)

__global__ __launch_bounds__(256, 2) void flash_part(
    const __half* __restrict__ C16, __half* __restrict__ Op,
    float2* __restrict__ ml)
{
    extern __shared__ char sm[];
    const uint32_t sb  = smem_to_u32(sm);
    const uint32_t sQ  = sb;
    const uint32_t sKV = sb + FQT;

    const int qi   = blockIdx.x >> 1;
    const int half = blockIdx.x & 1;
    const int qt   = NQ - 1 - qi;        // heaviest first
    const int q0   = qt * 128;
    const int h    = blockIdx.y;
    const int b    = blockIdx.z;
    const int kvh  = h >> 2;
    const int tid  = threadIdx.x;
    const int wid  = tid >> 5;
    const int lane = tid & 31;

    const int ntF = 2 * qt + 2;
    const int t0  = half ? ntF / 2 : 0;
    const int t1  = half ? ntF : ntF / 2;

    const __half* Kp = C16 + QDIM + kvh * HD;
    const __half* Vp = C16 + QDIM + KVDIM + kvh * HD;
    __half* Oph = Op + (size_t)half * MTOK * QDIM;
    float2* mlh = ml + (size_t)half * MTOK * NH;

#define KV_ISSUE(kt, buf) do { \
    uint32_t db = sKV + (uint32_t)(buf) * FKVST; \
    size_t gb = (size_t)(b * SS + (kt)) * QKVD; \
    _Pragma("unroll") \
    for (int j = 0; j < 4; j++) { \
        int i = tid + j * 256; \
        int rr = i >> 4, c16v = (i & 15) * 16; \
        size_t roff = gb + (size_t)rr * QKVD + (c16v >> 1); \
        cp16(db + rr * FROWB + c16v, Kp + roff); \
        cp16(db + FKT + rr * FROWB + c16v, Vp + roff); \
    } \
} while (0)

    // Q tile via cp.async: 128 rows x 16 chunks of 16B = 2048 chunks, 8/thread
    {
        size_t gq = (size_t)(b * SS + q0) * QKVD + h * HD;
#pragma unroll
        for (int j = 0; j < 8; j++) {
            int i = tid + j * 256;
            int rr = i >> 4, c16v = (i & 15) * 16;
            cp16(sQ + rr * FROWB + c16v, C16 + gq + (size_t)rr * QKVD + (c16v >> 1));
        }
    }
    CP_COMMIT();

    KV_ISSUE(t0 * 64, t0 & 1); CP_COMMIT();
    if (t0 + 1 < t1) { KV_ISSUE((t0 + 1) * 64, (t0 + 1) & 1); CP_COMMIT(); }

    const uint32_t a_off  = (uint32_t)((16 * wid + (lane & 7) + 8 * ((lane >> 3) & 1)) * FROWB
                                       + (lane >> 4) * 16);
    const uint32_t vt_off = (uint32_t)(((lane & 7) + 8 * ((lane >> 3) & 1)) * FROWB
                                       + (lane >> 4) * 16);
    const uint32_t b_off  = (uint32_t)(((lane & 7) + 8 * (lane >> 4)) * FROWB
                                       + ((lane >> 3) & 1) * 16);

    float o[16][4];
#pragma unroll
    for (int nf = 0; nf < 16; nf++)
#pragma unroll
        for (int r = 0; r < 4; r++) o[nf][r] = 0.f;
    float mo[2] = {-1e30f, -1e30f};
    float ls[2] = {0.f, 0.f};

    for (int t = t0; t < t1; t++) {
        const int kt = t * 64;
        if (t + 1 < t1) CP_WAIT(1); else CP_WAIT(0);
        __syncthreads();

        const uint32_t kvb = sKV + (uint32_t)(t & 1) * FKVST;
        const uint32_t cK = kvb, cV = kvb + FKT;

        float s[8][4];
#pragma unroll
        for (int f = 0; f < 8; f++)
#pragma unroll
            for (int r = 0; r < 4; r++) s[f][r] = 0.f;

#pragma unroll
        for (int ks = 0; ks < 8; ks++) {
            uint32_t qq[4];
            LDMX4(qq, sQ + a_off + ks * 32);
#pragma unroll
            for (int nb = 0; nb < 4; nb++) {
                uint32_t kk[4];
                LDMX4(kk, cK + b_off + nb * 16 * FROWB + ks * 32);
                MMA_F16(s[2 * nb],     qq, kk[0], kk[1]);
                MMA_F16(s[2 * nb + 1], qq, kk[2], kk[3]);
            }
        }

#pragma unroll
        for (int f = 0; f < 8; f++)
#pragma unroll
            for (int r = 0; r < 4; r++) s[f][r] *= SC_LOG2E;

        if (t >= ntF - 2) {
            const int row0 = q0 + 16 * wid + (lane >> 2);
            const int colb = kt + 2 * (lane & 3);
#pragma unroll
            for (int f = 0; f < 8; f++)
#pragma unroll
                for (int r = 0; r < 4; r++) {
                    int col = colb + 8 * f + (r & 1);
                    int row = row0 + 8 * (r >> 1);
                    if (col > row) s[f][r] = -1e30f;
                }
        }

#pragma unroll
        for (int hh = 0; hh < 2; hh++) {
            float mt = -1e30f;
#pragma unroll
            for (int f = 0; f < 8; f++)
                mt = fmaxf(mt, fmaxf(s[f][2 * hh], s[f][2 * hh + 1]));
            mt = fmaxf(mt, __shfl_xor_sync(0xffffffffu, mt, 1));
            mt = fmaxf(mt, __shfl_xor_sync(0xffffffffu, mt, 2));
            float mn = fmaxf(mo[hh], mt);
            float rs = 0.f;
#pragma unroll
            for (int f = 0; f < 8; f++) {
                float p0 = exp2f(s[f][2 * hh] - mn);
                float p1 = exp2f(s[f][2 * hh + 1] - mn);
                s[f][2 * hh] = p0;
                s[f][2 * hh + 1] = p1;
                rs += p0 + p1;
            }
            rs += __shfl_xor_sync(0xffffffffu, rs, 1);
            rs += __shfl_xor_sync(0xffffffffu, rs, 2);
            if (mt > mo[hh]) {
                float alpha = exp2f(mo[hh] - mn);
                ls[hh] = ls[hh] * alpha + rs;
                mo[hh] = mn;
#pragma unroll
                for (int nf = 0; nf < 16; nf++) {
                    o[nf][2 * hh]     *= alpha;
                    o[nf][2 * hh + 1] *= alpha;
                }
            } else {
                ls[hh] += rs;
            }
        }

#pragma unroll
        for (int ks = 0; ks < 4; ks++) {
            uint32_t ph[4];
            ph[0] = pack_h2(__float2half_rn(s[2 * ks][0]),     __float2half_rn(s[2 * ks][1]));
            ph[1] = pack_h2(__float2half_rn(s[2 * ks][2]),     __float2half_rn(s[2 * ks][3]));
            ph[2] = pack_h2(__float2half_rn(s[2 * ks + 1][0]), __float2half_rn(s[2 * ks + 1][1]));
            ph[3] = pack_h2(__float2half_rn(s[2 * ks + 1][2]), __float2half_rn(s[2 * ks + 1][3]));
#pragma unroll
            for (int nb = 0; nb < 8; nb++) {
                uint32_t vv[4];
                LDMX4T(vv, cV + vt_off + ks * 16 * FROWB + nb * 32);
                MMA_F16(o[2 * nb],     ph, vv[0], vv[1]);
                MMA_F16(o[2 * nb + 1], ph, vv[2], vv[3]);
            }
        }

        __syncthreads();
        if (t + 2 < t1) { KV_ISSUE((t + 2) * 64, t & 1); CP_COMMIT(); }
    }

    float inv0 = ls[0] > 0.f ? 1.f / ls[0] : 0.f;
    float inv1 = ls[1] > 0.f ? 1.f / ls[1] : 0.f;
#pragma unroll
    for (int nf = 0; nf < 16; nf++) {
#pragma unroll
        for (int rp = 0; rp < 2; rp++) {
            float invv = rp ? inv1 : inv0;
            float v0 = o[nf][2 * rp] * invv;
            float v1 = o[nf][2 * rp + 1] * invv;
            uint32_t hv = pack_h2(__float2half_rn(v0), __float2half_rn(v1));
            int row = q0 + 16 * wid + (lane >> 2) + 8 * rp;
            int col = h * HD + 8 * nf + 2 * (lane & 3);
            size_t g = (size_t)(b * SS + row) * QDIM + col;
            *(uint32_t*)(Oph + g) = hv;
        }
    }
    if ((lane & 3) == 0) {
#pragma unroll
        for (int rp = 0; rp < 2; rp++) {
            int row = q0 + 16 * wid + (lane >> 2) + 8 * rp;
            mlh[(size_t)(b * SS + row) * NH + h] = make_float2(mo[rp], ls[rp]);
        }
    }
#undef KV_ISSUE
}

// ---------------------------------------------------------------------------
// Split-KV combine: O = (w0*O0 + w1*O1)/(w0+w1), w_i = l_i * 2^(m_i - M)
// ---------------------------------------------------------------------------
__global__ void flash_combine(const __half* __restrict__ Op,
                              const float2* __restrict__ ml,
                              __half* __restrict__ O)
{
    int idx = blockIdx.x * blockDim.x + threadIdx.x;
    if (idx >= MTOK * NH * 16) return;
    int cg = idx & 15;
    int rh = idx >> 4;
    int h  = rh & (NH - 1);
    int m  = rh >> 4;

    float2 ml0 = ml[rh];
    float2 ml1 = ml[(size_t)MTOK * NH + rh];
    float M = fmaxf(ml0.x, ml1.x);
    float w0 = ml0.y * exp2f(ml0.x - M);
    float w1 = ml1.y * exp2f(ml1.x - M);
    float inv = 1.f / (w0 + w1);
    w0 *= inv; w1 *= inv;

    size_t off = ((size_t)m * QDIM + h * HD + cg * 8) >> 3;
    uint4 a = ((const uint4*)Op)[off];
    uint4 bq = ((const uint4*)(Op + (size_t)MTOK * QDIM))[off];

    uint4 r;
    uint32_t* ap = (uint32_t*)&a;
    uint32_t* bp = (uint32_t*)&bq;
    uint32_t* rp = (uint32_t*)&r;
#pragma unroll
    for (int j = 0; j < 4; j++) {
        __half2 ha = *(__half2*)&ap[j];
        __half2 hb = *(__half2*)&bp[j];
        float2 fa = __half22float2(ha);
        float2 fb = __half22float2(hb);
        rp[j] = pack_h2(__float2half_rn(fa.x * w0 + fb.x * w1),
                        __float2half_rn(fa.y * w0 + fb.y * w1));
    }
    ((uint4*)O)[off] = r;
}

// ---------------------------------------------------------------------------
// launcher
// ---------------------------------------------------------------------------
extern "C" void kernel_launch(void* const* d_in, const int* in_sizes, int n_in,
                              void* d_out, int out_size)
{
    const float* hidden = (const float*)d_in[0];
    const float* Wq     = (const float*)d_in[1];
    const float* Wk     = (const float*)d_in[2];
    const float* Wv     = (const float*)d_in[3];
    const float* Wo     = (const float*)d_in[4];
    const int*   pos    = (const int*)d_in[5];
    float* out = (float*)d_out;

    __half *C16, *H16, *W16, *Wo16, *O16, *Op;
    float2 *ml, *cs;
    cudaGetSymbolAddress((void**)&C16, g_C16);
    cudaGetSymbolAddress((void**)&H16, g_H16);
    cudaGetSymbolAddress((void**)&W16, g_W16);
    cudaGetSymbolAddress((void**)&Wo16, g_Wo16);
    cudaGetSymbolAddress((void**)&O16, g_O16);
    cudaGetSymbolAddress((void**)&Op, g_Op);
    cudaGetSymbolAddress((void**)&ml, g_ml);
    cudaGetSymbolAddress((void**)&cs, g_cs);

    cudaFuncSetAttribute(gemm_f16h,
                         cudaFuncAttributeMaxDynamicSharedMemorySize, GEMM_SMEM);
    cudaFuncSetAttribute(gemm_f16,
                         cudaFuncAttributeMaxDynamicSharedMemorySize, GEMM_SMEM);
    cudaFuncSetAttribute(flash_part,
                         cudaFuncAttributeMaxDynamicSharedMemorySize, FLASH_SMEM);

    // 1. conversions + rope table, one launch (2 items per thread)
    conv_all<<<(CHALF + 255) / 256, 256>>>(hidden, Wq, Wk, Wv, Wo, H16, W16, Wo16, cs);

    // 2. fused QKV projection -> fp16 C16 [MTOK, 3072] (unscale by 1/64)
    gemm_f16h<<<dim3(QKVD / 128, MTOK / 128), 256, GEMM_SMEM>>>(
        H16, W16, C16, MTOK, QKVD, HID, INV_WSCALE);

    // 3. RoPE in place on C16 (table-based, one launch)
    rope_all<<<(2 * MTOK * 64 + 255) / 256, 256>>>(C16, pos, cs);

    // 4. split-KV flash attention partials + combine
    flash_part<<<dim3(NQ * 2, NH, BB), 256, FLASH_SMEM>>>(C16, Op, ml);
    flash_combine<<<(MTOK * NH * 16 + 255) / 256, 256>>>(Op, ml, O16);

    // 5. output projection (unscale by 1/64)
    gemm_f16<<<dim3(HID / 128, MTOK / 128), 256, GEMM_SMEM>>>(
        O16, Wo16, out, MTOK, HID, QDIM, INV_WSCALE);
}